// round 5
// baseline (speedup 1.0000x reference)
#include <cuda_runtime.h>
#include <cuda_bf16.h>
#include <mma.h>
#include <cstdint>

using namespace nvcuda;

#define DF 128
#define MAXN 50000
#define MAXE 800000

// Scratch (allocation-free rule: __device__ globals)
__device__ __align__(16) float g_xws[MAXN * DF];   // (x@Wg) * dinv[row]
__device__ __align__(16) float g_agg[MAXN * DF];   // self-loop + sum over incoming edges
__device__ float g_dinv[MAXN];
__device__ int   g_ecnt[MAXN];
__device__ int   g_off[MAXN + 1];
__device__ int   g_cur[MAXN];
__device__ int   g_esrc[MAXE];
// bf16-split weights (hi + lo), original row-major layouts
__device__ __align__(16) __nv_bfloat16 g_wg_h[DF * DF], g_wg_l[DF * DF];   // Wg [k][n]
__device__ __align__(16) __nv_bfloat16 g_w1h[DF * DF],  g_w1l[DF * DF];    // W1 [k][n]
__device__ __align__(16) __nv_bfloat16 g_w2h[DF * 64],  g_w2l[DF * 64];    // W2 [k][n]

__device__ __forceinline__ void bsplit(float v, __nv_bfloat16& h, __nv_bfloat16& l) {
    h = __float2bfloat16_rn(v);
    l = __float2bfloat16_rn(v - __bfloat162float(h));
}

// ---------------------------------------------------------------------------
__global__ void k_zero_ecnt(int n) {
    int i = blockIdx.x * blockDim.x + threadIdx.x;
    if (i < n) g_ecnt[i] = 0;
}

__global__ void k_count(const int* __restrict__ ei, int e) {
    int i = blockIdx.x * blockDim.x + threadIdx.x;
    if (i < e) atomicAdd(&g_ecnt[ei[e + i]], 1);
}

// Split Wg, W1, W2 into bf16 hi/lo pairs.
__global__ void k_prepw(const float* __restrict__ Wg, const float* __restrict__ W1,
                        const float* __restrict__ W2) {
    int i = blockIdx.x * blockDim.x + threadIdx.x;
    if (i < 16384) {
        bsplit(Wg[i], g_wg_h[i], g_wg_l[i]);
    } else if (i < 32768) {
        int j = i - 16384;
        bsplit(W1[j], g_w1h[j], g_w1l[j]);
    } else if (i < 40960) {
        int j = i - 32768;
        bsplit(W2[j], g_w2h[j], g_w2l[j]);
    }
}

__global__ __launch_bounds__(1024) void k_scan(int n) {
    __shared__ int wsum[32];
    __shared__ int s_carry;
    int tid = threadIdx.x, lane = tid & 31, wid = tid >> 5;
    if (tid == 0) s_carry = 0;
    __syncthreads();
    for (int base = 0; base < n; base += 1024) {
        int i = base + tid;
        int v = (i < n) ? g_ecnt[i] : 0;
        int s = v;
#pragma unroll
        for (int d = 1; d < 32; d <<= 1) {
            int t = __shfl_up_sync(0xffffffffu, s, d);
            if (lane >= d) s += t;
        }
        if (lane == 31) wsum[wid] = s;
        __syncthreads();
        if (wid == 0) {
            int t = wsum[lane];
#pragma unroll
            for (int d = 1; d < 32; d <<= 1) {
                int u = __shfl_up_sync(0xffffffffu, t, d);
                if (lane >= d) t += u;
            }
            wsum[lane] = t;
        }
        __syncthreads();
        int excl = s - v + (wid ? wsum[wid - 1] : 0) + s_carry;
        if (i < n) {
            g_off[i] = excl;
            g_cur[i] = excl;
            g_dinv[i] = rsqrtf((float)(v + 1));
        }
        int total = wsum[31];
        __syncthreads();
        if (tid == 0) s_carry += total;
        __syncthreads();
    }
    if (threadIdx.x == 0) g_off[n] = s_carry;
}

__global__ void k_fill(const int* __restrict__ ei, int e) {
    int i = blockIdx.x * blockDim.x + threadIdx.x;
    if (i < e) {
        int s = ei[i];
        int d = ei[e + i];
        int pos = atomicAdd(&g_cur[d], 1);
        g_esrc[pos] = s;
    }
}

// ---------------------------------------------------------------------------
// Tensor-core GEMM via wmma bf16 split: xws = (x @ Wg) * dinv.
// 128 rows/block, 256 threads (8 warps). Each warp: one 16-row band x 8 col-tiles.
__global__ __launch_bounds__(256) void k_gemm_tc(const float* __restrict__ x, int n) {
    extern __shared__ char smem[];
    __nv_bfloat16* ah = (__nv_bfloat16*)smem;      // [128][128] hi   32KB
    __nv_bfloat16* al = ah + 16384;                //            lo   32KB
    __nv_bfloat16* bh = al + 16384;                // Wg hi           32KB
    __nv_bfloat16* bl = bh + 16384;                // Wg lo           32KB
    float* sout = (float*)(bl + 16384);            // [128][128] f32  64KB
    int tid = threadIdx.x;
    int rbase = blockIdx.x * 128;

    // weights -> smem
    {
        uint4* d0 = (uint4*)bh; const uint4* s0 = (const uint4*)g_wg_h;
        uint4* d1 = (uint4*)bl; const uint4* s1 = (const uint4*)g_wg_l;
        for (int i = tid; i < 2048; i += 256) { d0[i] = s0[i]; d1[i] = s1[i]; }
    }
    // x -> split into ah/al
    for (int i = tid; i < 4096; i += 256) {
        int r = i >> 5;            // row in tile
        int row = rbase + r;
        float4 v = (row < n) ? ((const float4*)x)[(size_t)row * 32 + (i & 31)]
                             : make_float4(0.f, 0.f, 0.f, 0.f);
        __nv_bfloat16 h0, l0, h1, l1, h2, l2, h3, l3;
        bsplit(v.x, h0, l0); bsplit(v.y, h1, l1);
        bsplit(v.z, h2, l2); bsplit(v.w, h3, l3);
        int o = i * 4;
        ah[o] = h0; ah[o + 1] = h1; ah[o + 2] = h2; ah[o + 3] = h3;
        al[o] = l0; al[o + 1] = l1; al[o + 2] = l2; al[o + 3] = l3;
    }
    __syncthreads();

    // MMA: D = AhBh + AhBl + AlBh
    {
        int w = tid >> 5;
        wmma::fragment<wmma::accumulator, 16, 16, 16, float> d[8];
#pragma unroll
        for (int ct = 0; ct < 8; ct++) wmma::fill_fragment(d[ct], 0.f);
#pragma unroll
        for (int k = 0; k < 8; k++) {
            wmma::fragment<wmma::matrix_a, 16, 16, 16, __nv_bfloat16, wmma::row_major> fah, fal;
            wmma::load_matrix_sync(fah, ah + (w * 16) * 128 + k * 16, 128);
            wmma::load_matrix_sync(fal, al + (w * 16) * 128 + k * 16, 128);
#pragma unroll
            for (int ct = 0; ct < 8; ct++) {
                wmma::fragment<wmma::matrix_b, 16, 16, 16, __nv_bfloat16, wmma::row_major> fbh, fbl;
                wmma::load_matrix_sync(fbh, bh + (k * 16) * 128 + ct * 16, 128);
                wmma::load_matrix_sync(fbl, bl + (k * 16) * 128 + ct * 16, 128);
                wmma::mma_sync(d[ct], fah, fbh, d[ct]);
                wmma::mma_sync(d[ct], fah, fbl, d[ct]);
                wmma::mma_sync(d[ct], fal, fbh, d[ct]);
            }
        }
#pragma unroll
        for (int ct = 0; ct < 8; ct++)
            wmma::store_matrix_sync(sout + (w * 16) * 128 + ct * 16, d[ct], 128,
                                    wmma::mem_row_major);
    }
    __syncthreads();

    // epilogue: scale by dinv, write
    for (int i = tid; i < 4096; i += 256) {
        int r = i >> 5;
        int row = rbase + r;
        if (row < n) {
            float dv = g_dinv[row];
            float4 v = ((const float4*)sout)[i];
            v.x *= dv; v.y *= dv; v.z *= dv; v.w *= dv;
            ((float4*)g_xws)[(size_t)row * 32 + (i & 31)] = v;
        }
    }
}

// ---------------------------------------------------------------------------
// One warp per dst node: agg[dst] = xws[dst] + sum_{e in CSR} xws[src].
__global__ __launch_bounds__(256) void k_aggregate(int n) {
    int w = (blockIdx.x * 256 + threadIdx.x) >> 5;
    int lane = threadIdx.x & 31;
    if (w >= n) return;
    const float4* xw4 = (const float4*)g_xws;
    float4 acc = xw4[(size_t)w * 32 + lane];
    int beg = g_off[w], end = g_off[w + 1];
    int j = beg;
    for (; j + 4 <= end; j += 4) {
        int s0 = g_esrc[j], s1 = g_esrc[j + 1], s2 = g_esrc[j + 2], s3 = g_esrc[j + 3];
        float4 v0 = xw4[(size_t)s0 * 32 + lane];
        float4 v1 = xw4[(size_t)s1 * 32 + lane];
        float4 v2 = xw4[(size_t)s2 * 32 + lane];
        float4 v3 = xw4[(size_t)s3 * 32 + lane];
        acc.x += v0.x + v1.x + v2.x + v3.x;
        acc.y += v0.y + v1.y + v2.y + v3.y;
        acc.z += v0.z + v1.z + v2.z + v3.z;
        acc.w += v0.w + v1.w + v2.w + v3.w;
    }
    for (; j < end; j++) {
        int s = g_esrc[j];
        float4 v = xw4[(size_t)s * 32 + lane];
        acc.x += v.x; acc.y += v.y; acc.z += v.z; acc.w += v.w;
    }
    ((float4*)g_agg)[(size_t)w * 32 + lane] = acc;
}

// ---------------------------------------------------------------------------
// Fused epilogue + MLP via wmma bf16 split. 128 nodes/block, 256 threads.
__global__ __launch_bounds__(256) void k_mlp(const float* __restrict__ x,
                                             const float* __restrict__ bg,
                                             const float* __restrict__ b1,
                                             const float* __restrict__ b2,
                                             const float* __restrict__ W3,
                                             const float* __restrict__ b3,
                                             float* __restrict__ out, int n) {
    extern __shared__ char smem[];
    __nv_bfloat16* ah = (__nv_bfloat16*)smem;      // act hi  [128][128] 32KB
    __nv_bfloat16* al = ah + 16384;                // act lo             32KB
    __nv_bfloat16* bh = al + 16384;                // W hi               32KB
    __nv_bfloat16* bl = bh + 16384;                // W lo               32KB
    float* sout = (float*)(bl + 16384);            // stage out f32      64KB
    float* sW3 = sout + 16384;   // 128
    float* sb1 = sW3 + 128;      // 128
    float* sbg = sb1 + 128;      // 128
    float* sb2 = sbg + 128;      // 64
    float* sb3 = sb2 + 64;       // 2
    int tid = threadIdx.x;
    int rbase = blockIdx.x * 128;

    // W1 -> smem; biases
    {
        uint4* d0 = (uint4*)bh; const uint4* s0 = (const uint4*)g_w1h;
        uint4* d1 = (uint4*)bl; const uint4* s1 = (const uint4*)g_w1l;
        for (int i = tid; i < 2048; i += 256) { d0[i] = s0[i]; d1[i] = s1[i]; }
        if (tid < 128) { sW3[tid] = W3[tid]; sb1[tid] = b1[tid]; sbg[tid] = bg[tid]; }
        else if (tid < 192) sb2[tid - 128] = b2[tid - 128];
        else if (tid < 194) sb3[tid - 192] = b3[tid - 192];
    }
    __syncthreads();

    // stage A: h = relu(dinv*agg + bg) + x, split -> ah/al
    for (int i = tid; i < 4096; i += 256) {
        int r = i >> 5;
        int node = rbase + r;
        float4 hv = make_float4(0.f, 0.f, 0.f, 0.f);
        if (node < n) {
            float dv = g_dinv[node];
            float4 a = ((const float4*)g_agg)[(size_t)node * 32 + (i & 31)];
            float4 xv = ((const float4*)x)[(size_t)node * 32 + (i & 31)];
            int c0 = (i & 31) * 4;
            hv.x = fmaxf(fmaf(dv, a.x, sbg[c0 + 0]), 0.f) + xv.x;
            hv.y = fmaxf(fmaf(dv, a.y, sbg[c0 + 1]), 0.f) + xv.y;
            hv.z = fmaxf(fmaf(dv, a.z, sbg[c0 + 2]), 0.f) + xv.z;
            hv.w = fmaxf(fmaf(dv, a.w, sbg[c0 + 3]), 0.f) + xv.w;
        }
        __nv_bfloat16 h0, l0, h1, l1, h2, l2, h3, l3;
        bsplit(hv.x, h0, l0); bsplit(hv.y, h1, l1);
        bsplit(hv.z, h2, l2); bsplit(hv.w, h3, l3);
        int o = i * 4;
        ah[o] = h0; ah[o + 1] = h1; ah[o + 2] = h2; ah[o + 3] = h3;
        al[o] = l0; al[o + 1] = l1; al[o + 2] = l2; al[o + 3] = l3;
    }
    __syncthreads();

    // stage B: h1_raw = h @ W1 -> sout
    {
        int w = tid >> 5;
        wmma::fragment<wmma::accumulator, 16, 16, 16, float> d[8];
#pragma unroll
        for (int ct = 0; ct < 8; ct++) wmma::fill_fragment(d[ct], 0.f);
#pragma unroll
        for (int k = 0; k < 8; k++) {
            wmma::fragment<wmma::matrix_a, 16, 16, 16, __nv_bfloat16, wmma::row_major> fah, fal;
            wmma::load_matrix_sync(fah, ah + (w * 16) * 128 + k * 16, 128);
            wmma::load_matrix_sync(fal, al + (w * 16) * 128 + k * 16, 128);
#pragma unroll
            for (int ct = 0; ct < 8; ct++) {
                wmma::fragment<wmma::matrix_b, 16, 16, 16, __nv_bfloat16, wmma::row_major> fbh, fbl;
                wmma::load_matrix_sync(fbh, bh + (k * 16) * 128 + ct * 16, 128);
                wmma::load_matrix_sync(fbl, bl + (k * 16) * 128 + ct * 16, 128);
                wmma::mma_sync(d[ct], fah, fbh, d[ct]);
                wmma::mma_sync(d[ct], fah, fbl, d[ct]);
                wmma::mma_sync(d[ct], fal, fbh, d[ct]);
            }
        }
#pragma unroll
        for (int ct = 0; ct < 8; ct++)
            wmma::store_matrix_sync(sout + (w * 16) * 128 + ct * 16, d[ct], 128,
                                    wmma::mem_row_major);
    }
    __syncthreads();

    // stage B2: h1 = relu(raw + b1), split -> ah/al; load W2 -> bh/bl
    for (int i = tid; i < 16384; i += 256) {
        float v = fmaxf(sout[i] + sb1[i & 127], 0.f);
        bsplit(v, ah[i], al[i]);
    }
    {
        uint4* d0 = (uint4*)bh; const uint4* s0 = (const uint4*)g_w2h;
        uint4* d1 = (uint4*)bl; const uint4* s1 = (const uint4*)g_w2l;
        for (int i = tid; i < 1024; i += 256) { d0[i] = s0[i]; d1[i] = s1[i]; }
    }
    __syncthreads();

    // stage C: h2_raw = h1 @ W2 -> sout[128][64]
    {
        int w = tid >> 5;
        wmma::fragment<wmma::accumulator, 16, 16, 16, float> d[4];
#pragma unroll
        for (int ct = 0; ct < 4; ct++) wmma::fill_fragment(d[ct], 0.f);
#pragma unroll
        for (int k = 0; k < 8; k++) {
            wmma::fragment<wmma::matrix_a, 16, 16, 16, __nv_bfloat16, wmma::row_major> fah, fal;
            wmma::load_matrix_sync(fah, ah + (w * 16) * 128 + k * 16, 128);
            wmma::load_matrix_sync(fal, al + (w * 16) * 128 + k * 16, 128);
#pragma unroll
            for (int ct = 0; ct < 4; ct++) {
                wmma::fragment<wmma::matrix_b, 16, 16, 16, __nv_bfloat16, wmma::row_major> fbh, fbl;
                wmma::load_matrix_sync(fbh, bh + (k * 16) * 64 + ct * 16, 64);
                wmma::load_matrix_sync(fbl, bl + (k * 16) * 64 + ct * 16, 64);
                wmma::mma_sync(d[ct], fah, fbh, d[ct]);
                wmma::mma_sync(d[ct], fah, fbl, d[ct]);
                wmma::mma_sync(d[ct], fal, fbh, d[ct]);
            }
        }
#pragma unroll
        for (int ct = 0; ct < 4; ct++)
            wmma::store_matrix_sync(sout + (w * 16) * 64 + ct * 16, d[ct], 64,
                                    wmma::mem_row_major);
    }
    __syncthreads();

    // stage D: out = relu(h2_raw + b2) @ W3 + b3
    if (tid < 256) {
        int r = tid >> 1, c = tid & 1;
        float a = sb3[c];
#pragma unroll
        for (int k = 0; k < 64; k++) {
            float h2 = fmaxf(sout[r * 64 + k] + sb2[k], 0.f);
            a = fmaf(h2, sW3[k * 2 + c], a);
        }
        int node = rbase + r;
        if (node < n) out[(size_t)c * n + node] = a;
    }
}

// ---------------------------------------------------------------------------
extern "C" void kernel_launch(void* const* d_in, const int* in_sizes, int n_in,
                              void* d_out, int out_size) {
    const float* x  = (const float*)d_in[0];
    const int*   ei = (const int*)d_in[1];
    const float* Wg = (const float*)d_in[2];
    const float* bg = (const float*)d_in[3];
    const float* W1 = (const float*)d_in[4];
    const float* b1 = (const float*)d_in[5];
    const float* W2 = (const float*)d_in[6];
    const float* b2 = (const float*)d_in[7];
    const float* W3 = (const float*)d_in[8];
    const float* b3 = (const float*)d_in[9];
    float* out = (float*)d_out;

    int n = in_sizes[0] / DF;
    int e = in_sizes[1] / 2;

    const int gemm_smem = 4 * 32768 + 65536;            // 196608
    const int mlp_smem  = 4 * 32768 + 65536 + 2048;     // 198656
    cudaFuncSetAttribute(k_gemm_tc, cudaFuncAttributeMaxDynamicSharedMemorySize, gemm_smem);
    cudaFuncSetAttribute(k_mlp, cudaFuncAttributeMaxDynamicSharedMemorySize, mlp_smem);

    k_zero_ecnt<<<(n + 255) / 256, 256>>>(n);
    k_count<<<(e + 255) / 256, 256>>>(ei, e);
    k_prepw<<<(40960 + 255) / 256, 256>>>(Wg, W1, W2);
    k_scan<<<1, 1024>>>(n);
    k_gemm_tc<<<(n + 127) / 128, 256, gemm_smem>>>(x, n);
    k_fill<<<(e + 255) / 256, 256>>>(ei, e);
    k_aggregate<<<(n + 7) / 8, 256>>>(n);
    k_mlp<<<(n + 127) / 128, 256, mlp_smem>>>(x, bg, b1, b2, W3, b3, out, n);
}

// round 6
// speedup vs baseline: 1.5924x; 1.5924x over previous
#include <cuda_runtime.h>
#include <cstdint>

#define DF 128
#define MAXN 50000
#define MAXE 800000

// Scratch (allocation-free rule: __device__ globals)
__device__ __align__(16) float g_xws[MAXN * DF];   // (x@Wg) * dinv[row]
__device__ __align__(16) float g_agg[MAXN * DF];   // self-loop + sum over incoming edges
__device__ float g_dinv[MAXN];
__device__ int   g_ecnt[MAXN];
__device__ int   g_off[MAXN + 1];
__device__ int   g_cur[MAXN];
__device__ int   g_esrc[MAXE];
__device__ int   g_bsum[64];
__device__ int   g_total;

// Packed fp32x2 FMA (SASS FFMA2): c += a * b on both lanes, exact fp32.
__device__ __forceinline__ void ffma2(float2& c, const float2 a, const float2 b) {
    asm("fma.rn.f32x2 %0, %1, %2, %0;"
        : "+l"(reinterpret_cast<unsigned long long&>(c))
        : "l"(reinterpret_cast<const unsigned long long&>(a)),
          "l"(reinterpret_cast<const unsigned long long&>(b)));
}

// ---------------------------------------------------------------------------
__global__ void k_zero_ecnt(int n) {
    int i = blockIdx.x * blockDim.x + threadIdx.x;
    if (i < n) g_ecnt[i] = 0;
}

__global__ void k_count(const int* __restrict__ ei, int e) {
    int i = blockIdx.x * blockDim.x + threadIdx.x;
    if (i < e) atomicAdd(&g_ecnt[ei[e + i]], 1);
}

// Multi-block scan, pass 1: per-block exclusive scan + block totals.
__global__ __launch_bounds__(1024) void k_scan1(int n) {
    __shared__ int wsum[32];
    int tid = threadIdx.x, lane = tid & 31, wid = tid >> 5;
    int i = blockIdx.x * 1024 + tid;
    int v = (i < n) ? g_ecnt[i] : 0;
    int s = v;
#pragma unroll
    for (int d = 1; d < 32; d <<= 1) {
        int t = __shfl_up_sync(0xffffffffu, s, d);
        if (lane >= d) s += t;
    }
    if (lane == 31) wsum[wid] = s;
    __syncthreads();
    if (wid == 0) {
        int t = wsum[lane];
#pragma unroll
        for (int d = 1; d < 32; d <<= 1) {
            int u = __shfl_up_sync(0xffffffffu, t, d);
            if (lane >= d) t += u;
        }
        wsum[lane] = t;
    }
    __syncthreads();
    int excl = s - v + (wid ? wsum[wid - 1] : 0);
    if (i < n) g_off[i] = excl;
    if (tid == 1023) g_bsum[blockIdx.x] = excl + v;  // block total
}

// Pass 2: serial exclusive scan of <=64 block totals (trivial).
__global__ void k_scan2(int nb) {
    if (threadIdx.x == 0 && blockIdx.x == 0) {
        int run = 0;
        for (int i = 0; i < nb; i++) { int t = g_bsum[i]; g_bsum[i] = run; run += t; }
        g_total = run;
    }
}

// Pass 3: add block offsets; emit off/cur/dinv; write sentinel.
__global__ __launch_bounds__(1024) void k_scan3(int n) {
    int i = blockIdx.x * 1024 + threadIdx.x;
    if (i < n) {
        int off = g_off[i] + g_bsum[blockIdx.x];
        g_off[i] = off;
        g_cur[i] = off;
        g_dinv[i] = rsqrtf((float)(g_ecnt[i] + 1));  // +1 self loop
    }
    if (i == 0) g_off[n] = g_total;
}

__global__ void k_fill(const int* __restrict__ ei, int e) {
    int i = blockIdx.x * blockDim.x + threadIdx.x;
    if (i < e) {
        int s = ei[i];
        int d = ei[e + i];
        int pos = atomicAdd(&g_cur[d], 1);
        g_esrc[pos] = s;
    }
}

// ---------------------------------------------------------------------------
// xws = (x @ Wg) * dinv[row]. 128 rows/block, 256 threads (8 warps).
// Warp tiling: 16 rows/warp, 4 cols/lane; k-step 4 with float4 x broadcasts.
__global__ __launch_bounds__(256) void k_gemm_xws(const float* __restrict__ x,
                                                  const float* __restrict__ Wg,
                                                  int n) {
    extern __shared__ float sm[];
    float* ws = sm;              // [128][128]
    float* xs = sm + 16384;      // [128][128]
    int tid = threadIdx.x;

    float4* ws4 = (float4*)ws;
    const float4* Wg4 = (const float4*)Wg;
    for (int i = tid; i < 4096; i += 256) ws4[i] = Wg4[i];

    int rbase = blockIdx.x * 128;
    float4* xs4 = (float4*)xs;
    const float4* x4 = (const float4*)x;
    for (int i = tid; i < 4096; i += 256) {
        int r = rbase + (i >> 5);
        xs4[i] = (r < n) ? x4[(size_t)r * 32 + (i & 31)]
                         : make_float4(0.f, 0.f, 0.f, 0.f);
    }
    __syncthreads();

    int w = tid >> 5, lane = tid & 31;
    float2 acc[16][2];
#pragma unroll
    for (int ri = 0; ri < 16; ri++) {
        acc[ri][0] = make_float2(0.f, 0.f);
        acc[ri][1] = make_float2(0.f, 0.f);
    }

    const float* xbase = xs + w * 16 * 128;
    for (int k0 = 0; k0 < 128; k0 += 4) {
        float4 wv[4];
#pragma unroll
        for (int kk = 0; kk < 4; kk++)
            wv[kk] = ((const float4*)(ws + (k0 + kk) * 128))[lane];
#pragma unroll
        for (int ri = 0; ri < 16; ri++) {
            float4 xv = *(const float4*)(xbase + ri * 128 + k0);
            ffma2(acc[ri][0], make_float2(xv.x, xv.x), make_float2(wv[0].x, wv[0].y));
            ffma2(acc[ri][1], make_float2(xv.x, xv.x), make_float2(wv[0].z, wv[0].w));
            ffma2(acc[ri][0], make_float2(xv.y, xv.y), make_float2(wv[1].x, wv[1].y));
            ffma2(acc[ri][1], make_float2(xv.y, xv.y), make_float2(wv[1].z, wv[1].w));
            ffma2(acc[ri][0], make_float2(xv.z, xv.z), make_float2(wv[2].x, wv[2].y));
            ffma2(acc[ri][1], make_float2(xv.z, xv.z), make_float2(wv[2].z, wv[2].w));
            ffma2(acc[ri][0], make_float2(xv.w, xv.w), make_float2(wv[3].x, wv[3].y));
            ffma2(acc[ri][1], make_float2(xv.w, xv.w), make_float2(wv[3].z, wv[3].w));
        }
    }

#pragma unroll
    for (int ri = 0; ri < 16; ri++) {
        int r = rbase + w * 16 + ri;
        if (r < n) {
            float dv = g_dinv[r];
            float4 o = make_float4(acc[ri][0].x * dv, acc[ri][0].y * dv,
                                   acc[ri][1].x * dv, acc[ri][1].y * dv);
            ((float4*)(g_xws + (size_t)r * 128))[lane] = o;
        }
    }
}

// ---------------------------------------------------------------------------
// One warp per dst node: agg[dst] = xws[dst] + sum_{e in CSR} xws[src].
__global__ __launch_bounds__(256) void k_aggregate(int n) {
    int w = (blockIdx.x * 256 + threadIdx.x) >> 5;
    int lane = threadIdx.x & 31;
    if (w >= n) return;
    const float4* xw4 = (const float4*)g_xws;
    float4 acc = xw4[(size_t)w * 32 + lane];
    int beg = g_off[w], end = g_off[w + 1];
    int j = beg;
    for (; j + 4 <= end; j += 4) {
        int s0 = g_esrc[j], s1 = g_esrc[j + 1], s2 = g_esrc[j + 2], s3 = g_esrc[j + 3];
        float4 v0 = xw4[(size_t)s0 * 32 + lane];
        float4 v1 = xw4[(size_t)s1 * 32 + lane];
        float4 v2 = xw4[(size_t)s2 * 32 + lane];
        float4 v3 = xw4[(size_t)s3 * 32 + lane];
        acc.x += v0.x + v1.x + v2.x + v3.x;
        acc.y += v0.y + v1.y + v2.y + v3.y;
        acc.z += v0.z + v1.z + v2.z + v3.z;
        acc.w += v0.w + v1.w + v2.w + v3.w;
    }
    for (; j < end; j++) {
        int s = g_esrc[j];
        float4 v = xw4[(size_t)s * 32 + lane];
        acc.x += v.x; acc.y += v.y; acc.z += v.z; acc.w += v.w;
    }
    ((float4*)g_agg)[(size_t)w * 32 + lane] = acc;
}

// ---------------------------------------------------------------------------
// Fused epilogue + 3-layer MLP. 128 nodes/block, 256 threads (8 warps).
__global__ __launch_bounds__(256) void k_mlp(const float* __restrict__ x,
                                             const float* __restrict__ bg,
                                             const float* __restrict__ W1,
                                             const float* __restrict__ b1,
                                             const float* __restrict__ W2,
                                             const float* __restrict__ b2,
                                             const float* __restrict__ W3,
                                             const float* __restrict__ b3,
                                             float* __restrict__ out, int n) {
    extern __shared__ float sm[];
    float* sW1 = sm;             // 16384
    float* sW2 = sW1 + 16384;    // 8192
    float* sh  = sW2 + 8192;     // 16384 (h; later reused as h2 [128][64])
    float* sh1 = sh + 16384;     // 16384
    float* sW3 = sh1 + 16384;    // 128
    float* sb1 = sW3 + 128;      // 128
    float* sbg = sb1 + 128;      // 128
    float* sb2 = sbg + 128;      // 64
    float* sb3 = sb2 + 64;       // 2
    int tid = threadIdx.x;
    int w = tid >> 5, lane = tid & 31;

    {
        float4* d4 = (float4*)sW1; const float4* s4 = (const float4*)W1;
        for (int i = tid; i < 4096; i += 256) d4[i] = s4[i];
        d4 = (float4*)sW2; s4 = (const float4*)W2;
        for (int i = tid; i < 2048; i += 256) d4[i] = s4[i];
        if (tid < 128) { sW3[tid] = W3[tid]; sb1[tid] = b1[tid]; sbg[tid] = bg[tid]; }
        else if (tid < 192) sb2[tid - 128] = b2[tid - 128];
        else if (tid < 194) sb3[tid - 192] = b3[tid - 192];
    }
    int rbase = blockIdx.x * 128;
    __syncthreads();

    // ---- stage A: h = relu(dinv*agg + bg) + x ----
    for (int i = tid; i < 4096; i += 256) {
        int r = i >> 5;
        int node = rbase + r;
        float4 hv = make_float4(0.f, 0.f, 0.f, 0.f);
        if (node < n) {
            float dv = g_dinv[node];
            float4 a = ((const float4*)g_agg)[(size_t)node * 32 + (i & 31)];
            float4 xv = ((const float4*)x)[(size_t)node * 32 + (i & 31)];
            int c0 = (i & 31) * 4;
            hv.x = fmaxf(fmaf(dv, a.x, sbg[c0 + 0]), 0.f) + xv.x;
            hv.y = fmaxf(fmaf(dv, a.y, sbg[c0 + 1]), 0.f) + xv.y;
            hv.z = fmaxf(fmaf(dv, a.z, sbg[c0 + 2]), 0.f) + xv.z;
            hv.w = fmaxf(fmaf(dv, a.w, sbg[c0 + 3]), 0.f) + xv.w;
        }
        ((float4*)sh)[i] = hv;
    }
    __syncthreads();

    // ---- stage B: h1 = relu(h @ W1 + b1), 16 rows/warp ----
    {
        float2 acc[16][2];
#pragma unroll
        for (int ri = 0; ri < 16; ri++) {
            acc[ri][0] = make_float2(0.f, 0.f);
            acc[ri][1] = make_float2(0.f, 0.f);
        }
        const float* hbase = sh + w * 16 * 128;
        for (int k0 = 0; k0 < 128; k0 += 4) {
            float4 wv[4];
#pragma unroll
            for (int kk = 0; kk < 4; kk++)
                wv[kk] = ((const float4*)(sW1 + (k0 + kk) * 128))[lane];
#pragma unroll
            for (int ri = 0; ri < 16; ri++) {
                float4 xv = *(const float4*)(hbase + ri * 128 + k0);
                ffma2(acc[ri][0], make_float2(xv.x, xv.x), make_float2(wv[0].x, wv[0].y));
                ffma2(acc[ri][1], make_float2(xv.x, xv.x), make_float2(wv[0].z, wv[0].w));
                ffma2(acc[ri][0], make_float2(xv.y, xv.y), make_float2(wv[1].x, wv[1].y));
                ffma2(acc[ri][1], make_float2(xv.y, xv.y), make_float2(wv[1].z, wv[1].w));
                ffma2(acc[ri][0], make_float2(xv.z, xv.z), make_float2(wv[2].x, wv[2].y));
                ffma2(acc[ri][1], make_float2(xv.z, xv.z), make_float2(wv[2].z, wv[2].w));
                ffma2(acc[ri][0], make_float2(xv.w, xv.w), make_float2(wv[3].x, wv[3].y));
                ffma2(acc[ri][1], make_float2(xv.w, xv.w), make_float2(wv[3].z, wv[3].w));
            }
        }
#pragma unroll
        for (int ri = 0; ri < 16; ri++) {
            int rr = w * 16 + ri;
            float4 o;
            o.x = fmaxf(acc[ri][0].x + sb1[lane * 4 + 0], 0.f);
            o.y = fmaxf(acc[ri][0].y + sb1[lane * 4 + 1], 0.f);
            o.z = fmaxf(acc[ri][1].x + sb1[lane * 4 + 2], 0.f);
            o.w = fmaxf(acc[ri][1].y + sb1[lane * 4 + 3], 0.f);
            ((float4*)(sh1 + rr * 128))[lane] = o;
        }
    }
    __syncthreads();

    // ---- stage C: h2 = relu(h1 @ W2 + b2) -> sh [128][64], 16 rows/warp, 2 cols/lane ----
    {
        float2 acc2[16];
#pragma unroll
        for (int ri = 0; ri < 16; ri++) acc2[ri] = make_float2(0.f, 0.f);
        const float* hbase = sh1 + w * 16 * 128;
        for (int k0 = 0; k0 < 128; k0 += 4) {
            float2 wv2[4];
#pragma unroll
            for (int kk = 0; kk < 4; kk++)
                wv2[kk] = ((const float2*)(sW2 + (k0 + kk) * 64))[lane];
#pragma unroll
            for (int ri = 0; ri < 16; ri++) {
                float4 xv = *(const float4*)(hbase + ri * 128 + k0);
                ffma2(acc2[ri], make_float2(xv.x, xv.x), wv2[0]);
                ffma2(acc2[ri], make_float2(xv.y, xv.y), wv2[1]);
                ffma2(acc2[ri], make_float2(xv.z, xv.z), wv2[2]);
                ffma2(acc2[ri], make_float2(xv.w, xv.w), wv2[3]);
            }
        }
#pragma unroll
        for (int ri = 0; ri < 16; ri++) {
            int rr = w * 16 + ri;
            float2 o;
            o.x = fmaxf(acc2[ri].x + sb2[lane * 2 + 0], 0.f);
            o.y = fmaxf(acc2[ri].y + sb2[lane * 2 + 1], 0.f);
            ((float2*)(sh + rr * 64))[lane] = o;
        }
    }
    __syncthreads();

    // ---- stage D: out = h2 @ W3 + b3 ----
    {
        int r = tid >> 1, c = tid & 1;
        float a = sb3[c];
#pragma unroll
        for (int k = 0; k < 64; k++) a = fmaf(sh[r * 64 + k], sW3[k * 2 + c], a);
        int node = rbase + r;
        if (node < n) out[(size_t)c * n + node] = a;
    }
}

// ---------------------------------------------------------------------------
extern "C" void kernel_launch(void* const* d_in, const int* in_sizes, int n_in,
                              void* d_out, int out_size) {
    const float* x  = (const float*)d_in[0];
    const int*   ei = (const int*)d_in[1];
    const float* Wg = (const float*)d_in[2];
    const float* bg = (const float*)d_in[3];
    const float* W1 = (const float*)d_in[4];
    const float* b1 = (const float*)d_in[5];
    const float* W2 = (const float*)d_in[6];
    const float* b2 = (const float*)d_in[7];
    const float* W3 = (const float*)d_in[8];
    const float* b3 = (const float*)d_in[9];
    float* out = (float*)d_out;

    int n = in_sizes[0] / DF;
    int e = in_sizes[1] / 2;
    int nb = (n + 1023) / 1024;

    const int gemm_smem = 2 * 16384 * 4;                              // 131072
    const int mlp_smem  = (16384 + 8192 + 16384 + 16384 + 450) * 4;   // 231176
    cudaFuncSetAttribute(k_gemm_xws, cudaFuncAttributeMaxDynamicSharedMemorySize, gemm_smem);
    cudaFuncSetAttribute(k_mlp, cudaFuncAttributeMaxDynamicSharedMemorySize, mlp_smem);

    k_zero_ecnt<<<(n + 255) / 256, 256>>>(n);
    k_count<<<(e + 255) / 256, 256>>>(ei, e);
    k_scan1<<<nb, 1024>>>(n);
    k_scan2<<<1, 32>>>(nb);
    k_scan3<<<nb, 1024>>>(n);
    k_gemm_xws<<<(n + 127) / 128, 256, gemm_smem>>>(x, Wg, n);
    k_fill<<<(e + 255) / 256, 256>>>(ei, e);
    k_aggregate<<<(n + 7) / 8, 256>>>(n);
    k_mlp<<<(n + 127) / 128, 256, mlp_smem>>>(x, bg, W1, b1, W2, b2, W3, b3, out, n);
}